// round 11
// baseline (speedup 1.0000x reference)
#include <cuda_runtime.h>
#include <cuda_bf16.h>
#include <cstdint>

#define B_    8192
#define F_    256
#define HALF_ 128
#define H_    512
#define K_    32768
#define L_    4
#define NSPLIT 16
#define TM 128
#define TN 128
#define TK 256
#define NT (K_ / NSPLIT / TN)   // 16 code tiles per CTA

#define STRB 528                // argmin tile row stride (bytes)
#define TILE_BYTES (128 * STRB) // 67584
#define SLICE (32 * STRB)       // 16896 (one warp-pair's 32-code slice)

#define HSTR 272                // hidden tile row stride: 128 bf16 + 16B pad
#define HTILE (128 * HSTR)      // 34816
#define SSTR 144                // st chunk row stride: 64 bf16 + 16B pad
#define STILE (128 * SSTR)      // 18432

// ---------------- scratch ----------------
__device__ float g_jac[B_];
__device__ float g_nb[K_];
__device__ float g_pmin[B_ * NSPLIT];
__device__ int   g_pidx[B_ * NSPLIT];
__device__ float g_partial[B_ / 8];
__device__ __nv_bfloat16 g_pb[K_ * F_];
__device__ __nv_bfloat16 g_xb[B_ * F_];
__device__ __nv_bfloat16 g_ah0[B_ * HALF_], g_al0[B_ * HALF_];
__device__ __nv_bfloat16 g_ah1[B_ * HALF_], g_al1[B_ * HALF_];
__device__ __nv_bfloat16 g_Hh[B_ * H_], g_Hl[B_ * H_];
__device__ float g_st[B_ * F_];
__device__ float g_y0[B_ * HALF_], g_y1[B_ * HALF_];
__device__ __nv_bfloat16 g_w1h[L_ * H_ * HALF_], g_w1l[L_ * H_ * HALF_];
__device__ __nv_bfloat16 g_wsh[L_ * HALF_ * H_], g_wsl[L_ * HALF_ * H_];
__device__ __nv_bfloat16 g_wth[L_ * HALF_ * H_], g_wtl[L_ * HALF_ * H_];

// ============ PTX helpers ============
__device__ __forceinline__ uint32_t smem_to_u32(const void* p) {
    uint32_t a;
    asm("{ .reg .u64 t; cvta.to.shared.u64 t, %1; cvt.u32.u64 %0, t; }" : "=r"(a) : "l"(p));
    return a;
}
__device__ __forceinline__ void cp16(uint32_t dst, const void* src) {
    asm volatile("cp.async.cg.shared.global [%0], [%1], 16;" :: "r"(dst), "l"(src));
}
#define CP_COMMIT() asm volatile("cp.async.commit_group;" ::: "memory")
#define CP_WAIT0()  asm volatile("cp.async.wait_group 0;" ::: "memory")
#define CP_WAIT1()  asm volatile("cp.async.wait_group 1;" ::: "memory")
#define PAIR_BAR(id) asm volatile("bar.sync %0, 64;" :: "r"(id) : "memory")

__device__ __forceinline__ void ldm_x4(uint32_t* r, uint32_t a) {
    asm volatile("ldmatrix.sync.aligned.m8n8.x4.shared.b16 {%0,%1,%2,%3}, [%4];"
        : "=r"(r[0]), "=r"(r[1]), "=r"(r[2]), "=r"(r[3]) : "r"(a));
}
__device__ __forceinline__ void mma_bf16(float* c, const uint32_t* a, const uint32_t* b) {
    asm volatile(
        "mma.sync.aligned.m16n8k16.row.col.f32.bf16.bf16.f32 "
        "{%0,%1,%2,%3}, {%4,%5,%6,%7}, {%8,%9}, {%0,%1,%2,%3};"
        : "+f"(c[0]), "+f"(c[1]), "+f"(c[2]), "+f"(c[3])
        : "r"(a[0]), "r"(a[1]), "r"(a[2]), "r"(a[3]), "r"(b[0]), "r"(b[1]));
}
__device__ __forceinline__ void bsplit(float v, __nv_bfloat16& h, __nv_bfloat16& l) {
    h = __float2bfloat16_rn(v);
    l = __float2bfloat16_rn(v - __bfloat162float(h));
}
__device__ __forceinline__ uint32_t pack_bf2(float a, float b) {
    __nv_bfloat162 t = __floats2bfloat162_rn(a, b);
    return *(uint32_t*)&t;
}

// ---------------- prep: fused ||p||^2 + bf16 convert (warp per code row) ----------------
__global__ __launch_bounds__(256) void nbcvt_kernel(
    const float* __restrict__ prior, __nv_bfloat16* __restrict__ dst)
{
    int warp = threadIdx.x >> 5, lane = threadIdx.x & 31;
    int row = blockIdx.x * 8 + warp;
    const float4* p = (const float4*)(prior + (size_t)row * F_);
    float4 a = p[lane * 2];
    float4 b = p[lane * 2 + 1];
    float s = 0.f;
    s = fmaf(a.x, a.x, s); s = fmaf(a.y, a.y, s);
    s = fmaf(a.z, a.z, s); s = fmaf(a.w, a.w, s);
    s = fmaf(b.x, b.x, s); s = fmaf(b.y, b.y, s);
    s = fmaf(b.z, b.z, s); s = fmaf(b.w, b.w, s);
#pragma unroll
    for (int off = 16; off; off >>= 1) s += __shfl_down_sync(0xffffffff, s, off);
    if (lane == 0) g_nb[row] = s;
    uint4 u;
    u.x = pack_bf2(a.x, a.y); u.y = pack_bf2(a.z, a.w);
    u.z = pack_bf2(b.x, b.y); u.w = pack_bf2(b.z, b.w);
    ((uint4*)(dst + (size_t)row * F_))[lane] = u;
}

// ---------------- prep: all 3 weight transpose+splits in one launch ----------------
__global__ __launch_bounds__(256) void wsplit3_kernel(
    const float* __restrict__ W1, const float* __restrict__ Ws, const float* __restrict__ Wt,
    __nv_bfloat16* __restrict__ w1h, __nv_bfloat16* __restrict__ w1l,
    __nv_bfloat16* __restrict__ wsh, __nv_bfloat16* __restrict__ wsl,
    __nv_bfloat16* __restrict__ wth, __nv_bfloat16* __restrict__ wtl)
{
    int which = blockIdx.y;
    const float* src = (which == 0) ? W1 : (which == 1) ? Ws : Wt;
    __nv_bfloat16* dh = (which == 0) ? w1h : (which == 1) ? wsh : wth;
    __nv_bfloat16* dl = (which == 0) ? w1l : (which == 1) ? wsl : wtl;
    int R = (which == 0) ? HALF_ : H_;
    int C = (which == 0) ? H_ : HALF_;
    int idx = blockIdx.x * 256 + threadIdx.x;
    int l = idx / (R * C); int rem = idx - l * R * C;
    int n = rem / R; int k = rem - n * R;
    float v = src[(size_t)l * R * C + (size_t)k * C + n];
    __nv_bfloat16 h, lo; bsplit(v, h, lo);
    dh[idx] = h; dl[idx] = lo;
}

// ---------------- prep: split xa (cols 0..127 of x0) ----------------
__global__ __launch_bounds__(256) void xsplit_kernel(
    const float* __restrict__ x0, __nv_bfloat16* __restrict__ ah, __nv_bfloat16* __restrict__ al)
{
    int idx = blockIdx.x * 256 + threadIdx.x;
    int r = idx >> 7, c = idx & 127;
    float v = x0[(size_t)r * F_ + c];
    __nv_bfloat16 h, l; bsplit(v, h, l);
    ah[idx] = h; al[idx] = l;
}

// ---------------- hidden: H = relu(xa@W1+b1), 3-slot smem (104KB -> 2 CTAs/SM) ----------------
// Slots: S1=Ah (persistent), S2=Bh then Bl, S3=Al. Segment order unchanged:
// sg0=Ah@Bh, sg1=Al@Bh, sg2=Ah@Bl -> bit-identical accumulation.
__global__ __launch_bounds__(256, 2) void hidden_mma_kernel(
    const __nv_bfloat16* __restrict__ ah, const __nv_bfloat16* __restrict__ al,
    const __nv_bfloat16* __restrict__ wh, const __nv_bfloat16* __restrict__ wl,
    const float* __restrict__ b1,
    __nv_bfloat16* __restrict__ HhOut, __nv_bfloat16* __restrict__ HlOut)
{
    extern __shared__ char sm[];
    uint32_t S1 = smem_to_u32(sm);          // Ah
    uint32_t S2 = S1 + HTILE;               // Bh -> Bl
    uint32_t S3 = S1 + 2 * HTILE;           // Al
    int tid = threadIdx.x, wid = tid >> 5, lane = tid & 31;
    int warp_m = wid & 1, warp_n = wid >> 1;
    int rowbase = blockIdx.x * 128;
    int nbase = blockIdx.y * 128;

    // group0: Ah + Bh ; group1: Al
#pragma unroll
    for (int i = 0; i < 8; i++) {
        int e = tid + i * 256; int r = e >> 4, c = e & 15;
        cp16(S1 + r * HSTR + c * 16, (const char*)(ah + (size_t)(rowbase + r) * HALF_) + c * 16);
        cp16(S2 + r * HSTR + c * 16, (const char*)(wh + (size_t)(nbase + r) * HALF_) + c * 16);
    }
    CP_COMMIT();
#pragma unroll
    for (int i = 0; i < 8; i++) {
        int e = tid + i * 256; int r = e >> 4, c = e & 15;
        cp16(S3 + r * HSTR + c * 16, (const char*)(al + (size_t)(rowbase + r) * HALF_) + c * 16);
    }
    CP_COMMIT();

    uint32_t aoff = (uint32_t)((warp_m * 64 + (lane & 15)) * HSTR + ((lane >> 4) * 8) * 2);
    uint32_t boff = (uint32_t)((warp_n * 32 + ((lane >> 4) & 1) * 8 + (lane & 7)) * HSTR
                               + (((lane >> 3) & 1) * 8) * 2);

    float acc[4][4][4];
#pragma unroll
    for (int mi = 0; mi < 4; mi++)
#pragma unroll
        for (int ni = 0; ni < 4; ni++)
#pragma unroll
            for (int q = 0; q < 4; q++) acc[mi][ni][q] = 0.f;

#define HID_SEG(Ab, Bb)                                                          \
    {                                                                            \
        _Pragma("unroll")                                                        \
        for (int kc = 0; kc < 8; kc++) {                                         \
            uint32_t kb = kc * 32;                                               \
            uint32_t afrag[4][4], bfrag[4][2];                                   \
            _Pragma("unroll")                                                    \
            for (int mi = 0; mi < 4; mi++)                                       \
                ldm_x4(afrag[mi], (Ab) + aoff + kb + (uint32_t)(mi * 16 * HSTR));\
            _Pragma("unroll")                                                    \
            for (int pr = 0; pr < 2; pr++) {                                     \
                uint32_t r4[4];                                                  \
                ldm_x4(r4, (Bb) + boff + kb + (uint32_t)(pr * 16 * HSTR));       \
                bfrag[pr * 2 + 0][0] = r4[0]; bfrag[pr * 2 + 0][1] = r4[1];      \
                bfrag[pr * 2 + 1][0] = r4[2]; bfrag[pr * 2 + 1][1] = r4[3];      \
            }                                                                    \
            _Pragma("unroll")                                                    \
            for (int mi = 0; mi < 4; mi++)                                       \
                _Pragma("unroll")                                                \
                for (int ni = 0; ni < 4; ni++)                                   \
                    mma_bf16(acc[mi][ni], afrag[mi], bfrag[ni]);                 \
        }                                                                        \
    }

    CP_WAIT1(); __syncthreads();     // Ah, Bh ready
    HID_SEG(S1, S2)                  // sg0: Ah @ Bh
    CP_WAIT0(); __syncthreads();     // Al ready
    HID_SEG(S3, S2)                  // sg1: Al @ Bh
    __syncthreads();                 // all warps done reading Bh
#pragma unroll
    for (int i = 0; i < 8; i++) {    // Bl into S2
        int e = tid + i * 256; int r = e >> 4, c = e & 15;
        cp16(S2 + r * HSTR + c * 16, (const char*)(wl + (size_t)(nbase + r) * HALF_) + c * 16);
    }
    CP_COMMIT(); CP_WAIT0(); __syncthreads();
    HID_SEG(S1, S2)                  // sg2: Ah @ Bl
#undef HID_SEG

#pragma unroll
    for (int mi = 0; mi < 4; mi++) {
        int r0 = rowbase + warp_m * 64 + mi * 16 + (lane >> 2);
#pragma unroll
        for (int ni = 0; ni < 4; ni++) {
            int c0 = nbase + warp_n * 32 + ni * 8 + (lane & 3) * 2;
            float bb0 = b1[c0], bb1 = b1[c0 + 1];
#pragma unroll
            for (int h = 0; h < 2; h++) {
                int r = r0 + h * 8;
                float v0 = acc[mi][ni][h * 2 + 0] + bb0; v0 = v0 > 0.f ? v0 : 0.f;
                float v1 = acc[mi][ni][h * 2 + 1] + bb1; v1 = v1 > 0.f ? v1 : 0.f;
                __nv_bfloat16 h0, h1, l0, l1;
                bsplit(v0, h0, l0); bsplit(v1, h1, l1);
                __nv_bfloat162 hv = __halves2bfloat162(h0, h1);
                __nv_bfloat162 lv = __halves2bfloat162(l0, l1);
                *(__nv_bfloat162*)(HhOut + (size_t)r * H_ + c0) = hv;
                *(__nv_bfloat162*)(HlOut + (size_t)r * H_ + c0) = lv;
            }
        }
    }
}

// ---------------- st: s_raw|t = H@Ws / H@Wt via split-bf16 mma ----------------
__device__ __forceinline__ void st_load_chunk(
    uint32_t Adst, uint32_t Bdst,
    const __nv_bfloat16* As, const __nv_bfloat16* Bs,
    int rowbase, int k0, int tid)
{
#pragma unroll
    for (int i = 0; i < 4; i++) {
        int e = tid + i * 256; int r = e >> 3, c = e & 7;
        cp16(Adst + r * SSTR + c * 16, (const char*)(As + (size_t)(rowbase + r) * H_ + k0) + c * 16);
        cp16(Bdst + r * SSTR + c * 16, (const char*)(Bs + (size_t)r * H_ + k0) + c * 16);
    }
}

__global__ __launch_bounds__(256, 2) void st_mma_kernel(
    const __nv_bfloat16* __restrict__ Hh, const __nv_bfloat16* __restrict__ Hl,
    const __nv_bfloat16* __restrict__ wsh, const __nv_bfloat16* __restrict__ wsl,
    const __nv_bfloat16* __restrict__ wth, const __nv_bfloat16* __restrict__ wtl,
    const float* __restrict__ bs, const float* __restrict__ bt,
    float* __restrict__ stout)
{
    extern __shared__ char sm[];
    uint32_t base = smem_to_u32(sm);
    uint32_t Ab0 = base,             Ab1 = base + STILE;
    uint32_t Bb0 = base + 2 * STILE, Bb1 = base + 3 * STILE;
    int tid = threadIdx.x, wid = tid >> 5, lane = tid & 31;
    int warp_m = wid & 1, warp_n = wid >> 1;
    int rowbase = blockIdx.x * 128;
    int ntile = blockIdx.y;
    const __nv_bfloat16* bwh = ntile ? wth : wsh;
    const __nv_bfloat16* bwl = ntile ? wtl : wsl;
    const float* bias = ntile ? bt : bs;

    st_load_chunk(Ab0, Bb0, Hh, bwh, rowbase, 0, tid);
    CP_COMMIT();

    uint32_t aoff = (uint32_t)((warp_m * 64 + (lane & 15)) * SSTR + ((lane >> 4) * 8) * 2);
    uint32_t boff = (uint32_t)((warp_n * 32 + ((lane >> 4) & 1) * 8 + (lane & 7)) * SSTR
                               + (((lane >> 3) & 1) * 8) * 2);

    float acc[4][4][4];
#pragma unroll
    for (int mi = 0; mi < 4; mi++)
#pragma unroll
        for (int ni = 0; ni < 4; ni++)
#pragma unroll
            for (int q = 0; q < 4; q++) acc[mi][ni][q] = 0.f;

    for (int idx = 0; idx < 24; idx++) {
        int cur = idx & 1;
        if (idx + 1 < 24) {
            int sg = (idx + 1) >> 3, k0 = ((idx + 1) & 7) * 64;
            const __nv_bfloat16* As = (sg == 1) ? Hl : Hh;
            const __nv_bfloat16* Bs = (sg == 2) ? bwl : bwh;
            st_load_chunk(cur ? Ab0 : Ab1, cur ? Bb0 : Bb1, As, Bs, rowbase, k0, tid);
            CP_COMMIT();
            CP_WAIT1();
        } else {
            CP_WAIT0();
        }
        __syncthreads();
        uint32_t Abc = cur ? Ab1 : Ab0;
        uint32_t Bbc = cur ? Bb1 : Bb0;
#pragma unroll
        for (int kc = 0; kc < 4; kc++) {
            uint32_t kb = kc * 32;
            uint32_t afrag[4][4], bfrag[4][2];
#pragma unroll
            for (int mi = 0; mi < 4; mi++)
                ldm_x4(afrag[mi], Abc + aoff + kb + (uint32_t)(mi * 16 * SSTR));
#pragma unroll
            for (int pr = 0; pr < 2; pr++) {
                uint32_t r4[4];
                ldm_x4(r4, Bbc + boff + kb + (uint32_t)(pr * 16 * SSTR));
                bfrag[pr * 2 + 0][0] = r4[0]; bfrag[pr * 2 + 0][1] = r4[1];
                bfrag[pr * 2 + 1][0] = r4[2]; bfrag[pr * 2 + 1][1] = r4[3];
            }
#pragma unroll
            for (int mi = 0; mi < 4; mi++)
#pragma unroll
                for (int ni = 0; ni < 4; ni++)
                    mma_bf16(acc[mi][ni], afrag[mi], bfrag[ni]);
        }
        __syncthreads();
    }

#pragma unroll
    for (int mi = 0; mi < 4; mi++) {
        int r0 = rowbase + warp_m * 64 + mi * 16 + (lane >> 2);
#pragma unroll
        for (int ni = 0; ni < 4; ni++) {
            int c0 = warp_n * 32 + ni * 8 + (lane & 3) * 2;
            float b0 = bias[c0], b1v = bias[c0 + 1];
#pragma unroll
            for (int h = 0; h < 2; h++) {
                int r = r0 + h * 8;
                float2 v;
                v.x = acc[mi][ni][h * 2 + 0] + b0;
                v.y = acc[mi][ni][h * 2 + 1] + b1v;
                *(float2*)(stout + (size_t)r * F_ + ntile * HALF_ + c0) = v;
            }
        }
    }
}

// ---------------- coupling epilogue ----------------
__global__ __launch_bounds__(256) void couple_kernel(
    const float* __restrict__ stin,
    const float* __restrict__ xa, int sxa,
    const float* __restrict__ xb, int sxb,
    float* __restrict__ yb,
    __nv_bfloat16* __restrict__ yh, __nv_bfloat16* __restrict__ yl,
    float* __restrict__ out, __nv_bfloat16* __restrict__ outb,
    int is_last, int accum)
{
    int warp = threadIdx.x >> 5, lane = threadIdx.x & 31;
    int r = blockIdx.x * 8 + warp;
    float4 s4 = ((const float4*)(stin + (size_t)r * F_))[lane];
    float4 t4 = ((const float4*)(stin + (size_t)r * F_ + HALF_))[lane];
    float4 xb4 = ((const float4*)(xb + (size_t)r * sxb))[lane];
    if (!is_last) {
        s4.x = tanhf(s4.x); s4.y = tanhf(s4.y);
        s4.z = tanhf(s4.z); s4.w = tanhf(s4.w);
    }
    float4 y;
    y.x = fmaf(xb4.x, expf(s4.x), t4.x);
    y.y = fmaf(xb4.y, expf(s4.y), t4.y);
    y.z = fmaf(xb4.z, expf(s4.z), t4.z);
    y.w = fmaf(xb4.w, expf(s4.w), t4.w);

    float js = s4.x + s4.y + s4.z + s4.w;
#pragma unroll
    for (int off = 16; off; off >>= 1) js += __shfl_down_sync(0xffffffff, js, off);
    if (lane == 0) g_jac[r] = accum ? g_jac[r] + js : js;

    if (!is_last) {
        ((float4*)(yb + (size_t)r * HALF_))[lane] = y;
        __nv_bfloat16 h0, h1, h2, h3, l0, l1, l2, l3;
        bsplit(y.x, h0, l0); bsplit(y.y, h1, l1);
        bsplit(y.z, h2, l2); bsplit(y.w, h3, l3);
        uint2 hv, lv;
        __nv_bfloat162 p01 = __halves2bfloat162(h0, h1), p23 = __halves2bfloat162(h2, h3);
        __nv_bfloat162 q01 = __halves2bfloat162(l0, l1), q23 = __halves2bfloat162(l2, l3);
        hv.x = *(uint32_t*)&p01; hv.y = *(uint32_t*)&p23;
        lv.x = *(uint32_t*)&q01; lv.y = *(uint32_t*)&q23;
        ((uint2*)(yh + (size_t)r * HALF_))[lane] = hv;
        ((uint2*)(yl + (size_t)r * HALF_))[lane] = lv;
    } else {
        float4 xa4 = ((const float4*)(xa + (size_t)r * sxa))[lane];
        ((float4*)(out + (size_t)r * F_))[lane] = y;
        ((float4*)(out + (size_t)r * F_ + HALF_))[lane] = xa4;
        uint2 u;
        u.x = pack_bf2(y.x, y.y); u.y = pack_bf2(y.z, y.w);
        ((uint2*)(outb + (size_t)r * F_))[lane] = u;
        u.x = pack_bf2(xa4.x, xa4.y); u.y = pack_bf2(xa4.z, xa4.w);
        ((uint2*)(outb + (size_t)r * F_ + HALF_))[lane] = u;
    }
}

// ---------------- bf16 mma distance GEMM + fused argmin (pair-decoupled, unchanged) ----------------
__global__ __launch_bounds__(256, 1) void argmin_mma_kernel(
    const __nv_bfloat16* __restrict__ xb, const __nv_bfloat16* __restrict__ pb)
{
    extern __shared__ char dsmem[];
    __shared__ __align__(16) float s_nb[4][2][32];
    __shared__ float redv[TM][4];
    __shared__ int   redi[TM][4];

    uint32_t Abase = smem_to_u32(dsmem);
    uint32_t Bregion = Abase + TILE_BYTES;

    int tid = threadIdx.x;
    int wid = tid >> 5, lane = tid & 31;
    int warp_m = wid & 1;
    int warp_n = wid >> 1;
    int pt = warp_m * 32 + lane;
    int rowbase = blockIdx.x * TM;
    int split = blockIdx.y;
    int code0 = split * (K_ / NSPLIT);
    int barid = 1 + warp_n;

    uint32_t sliceBase[2] = { Bregion + (uint32_t)(warp_n * 2 + 0) * SLICE,
                              Bregion + (uint32_t)(warp_n * 2 + 1) * SLICE };

#pragma unroll
    for (int i = 0; i < 16; i++) {
        int e = tid + i * 256;
        int r = e >> 5, c = e & 31;
        cp16(Abase + r * STRB + c * 16,
             (const char*)(xb + (size_t)(rowbase + r) * TK) + c * 16);
    }
#pragma unroll
    for (int i = 0; i < 16; i++) {
        int j = pt + i * 64;
        int r = j >> 5, c = j & 31;
        cp16(sliceBase[0] + r * STRB + c * 16,
             (const char*)(pb + (size_t)(code0 + warp_n * 32 + r) * TK) + c * 16);
    }
    if (pt < 32) s_nb[warp_n][0][pt] = g_nb[code0 + warp_n * 32 + pt];
    CP_COMMIT();
    CP_WAIT0();
    __syncthreads();

    uint32_t aoff = (uint32_t)((warp_m * 64 + (lane & 15)) * STRB + ((lane >> 4) * 8) * 2);
    uint32_t boff = (uint32_t)((((lane >> 4) & 1) * 8 + (lane & 7)) * STRB
                               + (((lane >> 3) & 1) * 8) * 2);

    float minv[8];
    int   mini[8];
#pragma unroll
    for (int i = 0; i < 8; i++) { minv[i] = 3.4e38f; mini[i] = 0; }

    for (int t = 0; t < NT; t++) {
        int cb = t & 1;
        if (t + 1 < NT) {
            int nb_ = (t + 1) & 1;
            int codeN = code0 + (t + 1) * TN;
#pragma unroll
            for (int i = 0; i < 16; i++) {
                int j = pt + i * 64;
                int r = j >> 5, c = j & 31;
                cp16(sliceBase[nb_] + r * STRB + c * 16,
                     (const char*)(pb + (size_t)(codeN + warp_n * 32 + r) * TK) + c * 16);
            }
            if (pt < 32) s_nb[warp_n][nb_][pt] = g_nb[codeN + warp_n * 32 + pt];
            CP_COMMIT();
            CP_WAIT1();
        } else {
            CP_WAIT0();
        }
        PAIR_BAR(barid);

        float acc[4][4][4];
#pragma unroll
        for (int mi = 0; mi < 4; mi++)
#pragma unroll
            for (int ni = 0; ni < 4; ni++)
#pragma unroll
                for (int q = 0; q < 4; q++) acc[mi][ni][q] = 0.f;

#pragma unroll
        for (int kc = 0; kc < 16; kc++) {
            uint32_t kb = kc * 32;
            uint32_t afrag[4][4], bfrag[4][2];
#pragma unroll
            for (int mi = 0; mi < 4; mi++)
                ldm_x4(afrag[mi], Abase + aoff + kb + (uint32_t)(mi * 16 * STRB));
#pragma unroll
            for (int pr = 0; pr < 2; pr++) {
                uint32_t r4[4];
                ldm_x4(r4, sliceBase[cb] + boff + kb + (uint32_t)(pr * 16 * STRB));
                bfrag[pr * 2 + 0][0] = r4[0]; bfrag[pr * 2 + 0][1] = r4[1];
                bfrag[pr * 2 + 1][0] = r4[2]; bfrag[pr * 2 + 1][1] = r4[3];
            }
#pragma unroll
            for (int mi = 0; mi < 4; mi++)
#pragma unroll
                for (int ni = 0; ni < 4; ni++)
                    mma_bf16(acc[mi][ni], afrag[mi], bfrag[ni]);
        }

        int ctile = code0 + t * TN;
#pragma unroll
        for (int mi = 0; mi < 4; mi++)
#pragma unroll
            for (int ni = 0; ni < 4; ni++)
#pragma unroll
                for (int q = 0; q < 4; q++) {
                    int nloc = ni * 8 + (lane & 3) * 2 + (q & 1);
                    float v = fmaf(-2.f, acc[mi][ni][q], s_nb[warp_n][cb][nloc]);
                    int ridx = mi * 2 + (q >> 1);
                    if (v < minv[ridx]) { minv[ridx] = v; mini[ridx] = ctile + warp_n * 32 + nloc; }
                }

        PAIR_BAR(barid);
    }

#pragma unroll
    for (int ridx = 0; ridx < 8; ridx++) {
        float v = minv[ridx]; int ii = mini[ridx];
#pragma unroll
        for (int off = 1; off <= 2; off <<= 1) {
            float ov = __shfl_xor_sync(0xffffffff, v, off);
            int   oi = __shfl_xor_sync(0xffffffff, ii, off);
            if (ov < v || (ov == v && oi < ii)) { v = ov; ii = oi; }
        }
        if ((lane & 3) == 0) {
            int row = warp_m * 64 + (ridx >> 1) * 16 + (ridx & 1) * 8 + (lane >> 2);
            redv[row][warp_n] = v;
            redi[row][warp_n] = ii;
        }
    }
    __syncthreads();
    if (tid < TM) {
        float bv = redv[tid][0]; int bi = redi[tid][0];
#pragma unroll
        for (int q = 1; q < 4; q++) {
            float v = redv[tid][q]; int ii = redi[tid][q];
            if (v < bv || (v == bv && ii < bi)) { bv = v; bi = ii; }
        }
        g_pmin[(size_t)(rowbase + tid) * NSPLIT + split] = bv;
        g_pidx[(size_t)(rowbase + tid) * NSPLIT + split] = bi;
    }
}

// ---------------- loss ----------------
__global__ __launch_bounds__(256) void loss_kernel(
    const float* __restrict__ x, const float* __restrict__ prior)
{
    int warp = threadIdx.x >> 5, lane = threadIdx.x & 31;
    int r = blockIdx.x * 8 + warp;
    float v = 3.4e38f; int idx = 0x7fffffff;
    if (lane < NSPLIT) { v = g_pmin[(size_t)r * NSPLIT + lane]; idx = g_pidx[(size_t)r * NSPLIT + lane]; }
#pragma unroll
    for (int off = 8; off; off >>= 1) {
        float ov = __shfl_down_sync(0xffffffff, v, off);
        int   oi = __shfl_down_sync(0xffffffff, idx, off);
        if (ov < v || (ov == v && oi < idx)) { v = ov; idx = oi; }
    }
    idx = __shfl_sync(0xffffffff, idx, 0);
    float ss = 0.f;
#pragma unroll
    for (int f = lane; f < F_; f += 32) {
        float d = x[(size_t)r * F_ + f] - prior[(size_t)idx * F_ + f];
        ss = fmaf(d, d, ss);
    }
#pragma unroll
    for (int off = 16; off; off >>= 1) ss += __shfl_down_sync(0xffffffff, ss, off);
    __shared__ float part[8];
    if (lane == 0) part[warp] = fmaf(0.625f, ss, -g_jac[r]);
    __syncthreads();
    if (threadIdx.x == 0) {
        float s = 0.f;
#pragma unroll
        for (int i = 0; i < 8; i++) s += part[i];
        g_partial[blockIdx.x] = s;
    }
}

__global__ __launch_bounds__(256) void final_kernel(float* out, int out_size) {
    __shared__ float sm[256];
    int tid = threadIdx.x;
    float s = 0.f;
    for (int i = tid; i < B_ / 8; i += 256) s += g_partial[i];
    sm[tid] = s;
    __syncthreads();
    for (int st = 128; st; st >>= 1) { if (tid < st) sm[tid] += sm[tid + st]; __syncthreads(); }
    float loss = sm[0] / (float)B_;
    for (int i = B_ * F_ + tid; i < out_size; i += 256) out[i] = loss;
}

// ---------------- launch ----------------
static void* sym(const void* s) { void* p; cudaGetSymbolAddress(&p, s); return p; }

extern "C" void kernel_launch(void* const* d_in, const int* in_sizes, int n_in,
                              void* d_out, int out_size) {
    const float* x0    = (const float*)d_in[0];
    const float* W1    = (const float*)d_in[1];
    const float* b1    = (const float*)d_in[2];
    const float* Ws    = (const float*)d_in[3];
    const float* bs    = (const float*)d_in[4];
    const float* Wt    = (const float*)d_in[5];
    const float* bt    = (const float*)d_in[6];
    const float* prior = (const float*)d_in[7];
    float* out = (float*)d_out;

    __nv_bfloat16* gpb  = (__nv_bfloat16*)sym(g_pb);
    __nv_bfloat16* gxb  = (__nv_bfloat16*)sym(g_xb);
    __nv_bfloat16* ahB[2] = { (__nv_bfloat16*)sym(g_ah0), (__nv_bfloat16*)sym(g_ah1) };
    __nv_bfloat16* alB[2] = { (__nv_bfloat16*)sym(g_al0), (__nv_bfloat16*)sym(g_al1) };
    __nv_bfloat16* gHh  = (__nv_bfloat16*)sym(g_Hh);
    __nv_bfloat16* gHl  = (__nv_bfloat16*)sym(g_Hl);
    float* gst = (float*)sym(g_st);
    float* yB[2] = { (float*)sym(g_y0), (float*)sym(g_y1) };
    __nv_bfloat16* w1h = (__nv_bfloat16*)sym(g_w1h);
    __nv_bfloat16* w1l = (__nv_bfloat16*)sym(g_w1l);
    __nv_bfloat16* wsh = (__nv_bfloat16*)sym(g_wsh);
    __nv_bfloat16* wsl = (__nv_bfloat16*)sym(g_wsl);
    __nv_bfloat16* wth = (__nv_bfloat16*)sym(g_wth);
    __nv_bfloat16* wtl = (__nv_bfloat16*)sym(g_wtl);

    static int smem_set = 0;
    const int ASMEM = TILE_BYTES + 8 * SLICE;   // 202752
    const int HSMEM = 3 * HTILE;                // 104448 -> 2 CTAs/SM
    const int SSMEM = 4 * STILE;                // 73728
    if (!smem_set) {
        cudaFuncSetAttribute(argmin_mma_kernel, cudaFuncAttributeMaxDynamicSharedMemorySize, ASMEM);
        cudaFuncSetAttribute(hidden_mma_kernel, cudaFuncAttributeMaxDynamicSharedMemorySize, HSMEM);
        cudaFuncSetAttribute(st_mma_kernel, cudaFuncAttributeMaxDynamicSharedMemorySize, SSMEM);
        smem_set = 1;
    }

    // prep (consolidated)
    nbcvt_kernel<<<K_ / 8, 256>>>(prior, gpb);
    wsplit3_kernel<<<dim3((L_ * HALF_ * H_) / 256, 3), 256>>>(
        W1, Ws, Wt, w1h, w1l, wsh, wsl, wth, wtl);
    xsplit_kernel<<<(B_ * HALF_) / 256, 256>>>(x0, ahB[0], alB[0]);

    // flow
    const float* XA = x0;        int sxa = F_;
    const float* XB = x0 + HALF_; int sxb = F_;
    for (int l = 0; l < L_; l++) {
        hidden_mma_kernel<<<dim3(B_ / 128, H_ / 128), 256, HSMEM>>>(
            ahB[l & 1], alB[l & 1],
            w1h + (size_t)l * H_ * HALF_, w1l + (size_t)l * H_ * HALF_,
            b1 + (size_t)l * H_, gHh, gHl);
        st_mma_kernel<<<dim3(B_ / 128, 2), 256, SSMEM>>>(
            gHh, gHl,
            wsh + (size_t)l * HALF_ * H_, wsl + (size_t)l * HALF_ * H_,
            wth + (size_t)l * HALF_ * H_, wtl + (size_t)l * HALF_ * H_,
            bs + (size_t)l * HALF_, bt + (size_t)l * HALF_, gst);
        int last = (l == L_ - 1);
        couple_kernel<<<B_ / 8, 256>>>(
            gst, XA, sxa, XB, sxb,
            yB[l & 1], ahB[(l + 1) & 1], alB[(l + 1) & 1],
            out, gxb, last, l > 0);
        XB = XA; sxb = sxa;
        XA = yB[l & 1]; sxa = HALF_;
    }

    // VQ argmin + loss
    argmin_mma_kernel<<<dim3(B_ / TM, NSPLIT), 256, ASMEM>>>(gxb, gpb);
    loss_kernel<<<B_ / 8, 256>>>(out, prior);
    if (out_size > B_ * F_)
        final_kernel<<<1, 256>>>(out, out_size);
}

// round 12
// speedup vs baseline: 1.5087x; 1.5087x over previous
#include <cuda_runtime.h>
#include <cuda_bf16.h>
#include <cstdint>

#define B_    8192
#define F_    256
#define HALF_ 128
#define H_    512
#define K_    32768
#define L_    4
#define NSPLIT 16
#define TM 128
#define TN 128
#define TK 256
#define NT (K_ / NSPLIT / TN)   // 16 code tiles per CTA

#define STRB 528                // argmin tile row stride (bytes)
#define TILE_BYTES (128 * STRB) // 67584
#define SLICE (32 * STRB)       // 16896 (one warp-pair's 32-code slice)

#define HSTR 272                // hidden tile row stride: 128 bf16 + 16B pad
#define HTILE (128 * HSTR)      // 34816
#define SSTR 144                // st chunk row stride: 64 bf16 + 16B pad
#define STILE (128 * SSTR)      // 18432

// ---------------- scratch ----------------
__device__ float g_jac[B_];
__device__ float g_nb[K_];
__device__ float g_pmin[B_ * NSPLIT];
__device__ int   g_pidx[B_ * NSPLIT];
__device__ float g_partial[B_ / 8];
__device__ __nv_bfloat16 g_pb[K_ * F_];
__device__ __nv_bfloat16 g_xb[B_ * F_];
__device__ __nv_bfloat16 g_ah0[B_ * HALF_], g_al0[B_ * HALF_];
__device__ __nv_bfloat16 g_ah1[B_ * HALF_], g_al1[B_ * HALF_];
__device__ __nv_bfloat16 g_Hh[B_ * H_], g_Hl[B_ * H_];
__device__ float g_st[B_ * F_];
__device__ float g_y0[B_ * HALF_], g_y1[B_ * HALF_];
__device__ __nv_bfloat16 g_w1h[L_ * H_ * HALF_], g_w1l[L_ * H_ * HALF_];
__device__ __nv_bfloat16 g_wsh[L_ * HALF_ * H_], g_wsl[L_ * HALF_ * H_];
__device__ __nv_bfloat16 g_wth[L_ * HALF_ * H_], g_wtl[L_ * HALF_ * H_];

// ============ PTX helpers ============
__device__ __forceinline__ uint32_t smem_to_u32(const void* p) {
    uint32_t a;
    asm("{ .reg .u64 t; cvta.to.shared.u64 t, %1; cvt.u32.u64 %0, t; }" : "=r"(a) : "l"(p));
    return a;
}
__device__ __forceinline__ void cp16(uint32_t dst, const void* src) {
    asm volatile("cp.async.cg.shared.global [%0], [%1], 16;" :: "r"(dst), "l"(src));
}
#define CP_COMMIT() asm volatile("cp.async.commit_group;" ::: "memory")
#define CP_WAIT0()  asm volatile("cp.async.wait_group 0;" ::: "memory")
#define CP_WAIT1()  asm volatile("cp.async.wait_group 1;" ::: "memory")
#define PAIR_BAR(id) asm volatile("bar.sync %0, 64;" :: "r"(id) : "memory")

__device__ __forceinline__ void ldm_x4(uint32_t* r, uint32_t a) {
    asm volatile("ldmatrix.sync.aligned.m8n8.x4.shared.b16 {%0,%1,%2,%3}, [%4];"
        : "=r"(r[0]), "=r"(r[1]), "=r"(r[2]), "=r"(r[3]) : "r"(a));
}
__device__ __forceinline__ void mma_bf16(float* c, const uint32_t* a, const uint32_t* b) {
    asm volatile(
        "mma.sync.aligned.m16n8k16.row.col.f32.bf16.bf16.f32 "
        "{%0,%1,%2,%3}, {%4,%5,%6,%7}, {%8,%9}, {%0,%1,%2,%3};"
        : "+f"(c[0]), "+f"(c[1]), "+f"(c[2]), "+f"(c[3])
        : "r"(a[0]), "r"(a[1]), "r"(a[2]), "r"(a[3]), "r"(b[0]), "r"(b[1]));
}
__device__ __forceinline__ void bsplit(float v, __nv_bfloat16& h, __nv_bfloat16& l) {
    h = __float2bfloat16_rn(v);
    l = __float2bfloat16_rn(v - __bfloat162float(h));
}
__device__ __forceinline__ uint32_t pack_bf2(float a, float b) {
    __nv_bfloat162 t = __floats2bfloat162_rn(a, b);
    return *(uint32_t*)&t;
}

// ---------------- prep: fused ||p||^2 + bf16 convert (warp per code row) ----------------
__global__ __launch_bounds__(256) void nbcvt_kernel(
    const float* __restrict__ prior, __nv_bfloat16* __restrict__ dst)
{
    int warp = threadIdx.x >> 5, lane = threadIdx.x & 31;
    int row = blockIdx.x * 8 + warp;
    const float4* p = (const float4*)(prior + (size_t)row * F_);
    float4 a = p[lane * 2];
    float4 b = p[lane * 2 + 1];
    float s = 0.f;
    s = fmaf(a.x, a.x, s); s = fmaf(a.y, a.y, s);
    s = fmaf(a.z, a.z, s); s = fmaf(a.w, a.w, s);
    s = fmaf(b.x, b.x, s); s = fmaf(b.y, b.y, s);
    s = fmaf(b.z, b.z, s); s = fmaf(b.w, b.w, s);
#pragma unroll
    for (int off = 16; off; off >>= 1) s += __shfl_down_sync(0xffffffff, s, off);
    if (lane == 0) g_nb[row] = s;
    uint4 u;
    u.x = pack_bf2(a.x, a.y); u.y = pack_bf2(a.z, a.w);
    u.z = pack_bf2(b.x, b.y); u.w = pack_bf2(b.z, b.w);
    ((uint4*)(dst + (size_t)row * F_))[lane] = u;
}

// ---------------- prep: all 3 weight transpose+splits in one launch ----------------
__global__ __launch_bounds__(256) void wsplit3_kernel(
    const float* __restrict__ W1, const float* __restrict__ Ws, const float* __restrict__ Wt,
    __nv_bfloat16* __restrict__ w1h, __nv_bfloat16* __restrict__ w1l,
    __nv_bfloat16* __restrict__ wsh, __nv_bfloat16* __restrict__ wsl,
    __nv_bfloat16* __restrict__ wth, __nv_bfloat16* __restrict__ wtl)
{
    int which = blockIdx.y;
    const float* src = (which == 0) ? W1 : (which == 1) ? Ws : Wt;
    __nv_bfloat16* dh = (which == 0) ? w1h : (which == 1) ? wsh : wth;
    __nv_bfloat16* dl = (which == 0) ? w1l : (which == 1) ? wsl : wtl;
    int R = (which == 0) ? HALF_ : H_;
    int C = (which == 0) ? H_ : HALF_;
    int idx = blockIdx.x * 256 + threadIdx.x;
    int l = idx / (R * C); int rem = idx - l * R * C;
    int n = rem / R; int k = rem - n * R;
    float v = src[(size_t)l * R * C + (size_t)k * C + n];
    __nv_bfloat16 h, lo; bsplit(v, h, lo);
    dh[idx] = h; dl[idx] = lo;
}

// ---------------- prep: split xa (cols 0..127 of x0) ----------------
__global__ __launch_bounds__(256) void xsplit_kernel(
    const float* __restrict__ x0, __nv_bfloat16* __restrict__ ah, __nv_bfloat16* __restrict__ al)
{
    int idx = blockIdx.x * 256 + threadIdx.x;
    int r = idx >> 7, c = idx & 127;
    float v = x0[(size_t)r * F_ + c];
    __nv_bfloat16 h, l; bsplit(v, h, l);
    ah[idx] = h; al[idx] = l;
}

// ---------------- hidden: H = relu(xa@W1+b1) via split-bf16 mma ----------------
__global__ __launch_bounds__(256, 2) void hidden_mma_kernel(
    const __nv_bfloat16* __restrict__ ah, const __nv_bfloat16* __restrict__ al,
    const __nv_bfloat16* __restrict__ wh, const __nv_bfloat16* __restrict__ wl,
    const float* __restrict__ b1,
    __nv_bfloat16* __restrict__ HhOut, __nv_bfloat16* __restrict__ HlOut)
{
    extern __shared__ char sm[];
    uint32_t Ahs = smem_to_u32(sm);
    uint32_t Als = Ahs + HTILE;
    uint32_t Bhs = Ahs + 2 * HTILE;
    uint32_t Bls = Ahs + 3 * HTILE;
    int tid = threadIdx.x, wid = tid >> 5, lane = tid & 31;
    int warp_m = wid & 1, warp_n = wid >> 1;
    int rowbase = blockIdx.x * 128;
    int nbase = blockIdx.y * 128;

#pragma unroll
    for (int i = 0; i < 8; i++) {
        int e = tid + i * 256; int r = e >> 4, c = e & 15;
        cp16(Ahs + r * HSTR + c * 16, (const char*)(ah + (size_t)(rowbase + r) * HALF_) + c * 16);
        cp16(Als + r * HSTR + c * 16, (const char*)(al + (size_t)(rowbase + r) * HALF_) + c * 16);
        cp16(Bhs + r * HSTR + c * 16, (const char*)(wh + (size_t)(nbase + r) * HALF_) + c * 16);
        cp16(Bls + r * HSTR + c * 16, (const char*)(wl + (size_t)(nbase + r) * HALF_) + c * 16);
    }
    CP_COMMIT(); CP_WAIT0(); __syncthreads();

    uint32_t aoff = (uint32_t)((warp_m * 64 + (lane & 15)) * HSTR + ((lane >> 4) * 8) * 2);
    uint32_t boff = (uint32_t)((warp_n * 32 + ((lane >> 4) & 1) * 8 + (lane & 7)) * HSTR
                               + (((lane >> 3) & 1) * 8) * 2);

    float acc[4][4][4];
#pragma unroll
    for (int mi = 0; mi < 4; mi++)
#pragma unroll
        for (int ni = 0; ni < 4; ni++)
#pragma unroll
            for (int q = 0; q < 4; q++) acc[mi][ni][q] = 0.f;

#pragma unroll
    for (int sg = 0; sg < 3; sg++) {
        uint32_t Ab = (sg == 1) ? Als : Ahs;
        uint32_t Bb = (sg == 2) ? Bls : Bhs;
#pragma unroll
        for (int kc = 0; kc < 8; kc++) {
            uint32_t kb = kc * 32;
            uint32_t afrag[4][4], bfrag[4][2];
#pragma unroll
            for (int mi = 0; mi < 4; mi++)
                ldm_x4(afrag[mi], Ab + aoff + kb + (uint32_t)(mi * 16 * HSTR));
#pragma unroll
            for (int pr = 0; pr < 2; pr++) {
                uint32_t r4[4];
                ldm_x4(r4, Bb + boff + kb + (uint32_t)(pr * 16 * HSTR));
                bfrag[pr * 2 + 0][0] = r4[0]; bfrag[pr * 2 + 0][1] = r4[1];
                bfrag[pr * 2 + 1][0] = r4[2]; bfrag[pr * 2 + 1][1] = r4[3];
            }
#pragma unroll
            for (int mi = 0; mi < 4; mi++)
#pragma unroll
                for (int ni = 0; ni < 4; ni++)
                    mma_bf16(acc[mi][ni], afrag[mi], bfrag[ni]);
        }
    }

#pragma unroll
    for (int mi = 0; mi < 4; mi++) {
        int r0 = rowbase + warp_m * 64 + mi * 16 + (lane >> 2);
#pragma unroll
        for (int ni = 0; ni < 4; ni++) {
            int c0 = nbase + warp_n * 32 + ni * 8 + (lane & 3) * 2;
            float bb0 = b1[c0], bb1 = b1[c0 + 1];
#pragma unroll
            for (int h = 0; h < 2; h++) {
                int r = r0 + h * 8;
                float v0 = acc[mi][ni][h * 2 + 0] + bb0; v0 = v0 > 0.f ? v0 : 0.f;
                float v1 = acc[mi][ni][h * 2 + 1] + bb1; v1 = v1 > 0.f ? v1 : 0.f;
                __nv_bfloat16 h0, h1, l0, l1;
                bsplit(v0, h0, l0); bsplit(v1, h1, l1);
                __nv_bfloat162 hv = __halves2bfloat162(h0, h1);
                __nv_bfloat162 lv = __halves2bfloat162(l0, l1);
                *(__nv_bfloat162*)(HhOut + (size_t)r * H_ + c0) = hv;
                *(__nv_bfloat162*)(HlOut + (size_t)r * H_ + c0) = lv;
            }
        }
    }
}

// ---------------- st: s_raw|t = H@Ws / H@Wt via split-bf16 mma ----------------
__device__ __forceinline__ void st_load_chunk(
    uint32_t Adst, uint32_t Bdst,
    const __nv_bfloat16* As, const __nv_bfloat16* Bs,
    int rowbase, int k0, int tid)
{
#pragma unroll
    for (int i = 0; i < 4; i++) {
        int e = tid + i * 256; int r = e >> 3, c = e & 7;
        cp16(Adst + r * SSTR + c * 16, (const char*)(As + (size_t)(rowbase + r) * H_ + k0) + c * 16);
        cp16(Bdst + r * SSTR + c * 16, (const char*)(Bs + (size_t)r * H_ + k0) + c * 16);
    }
}

__global__ __launch_bounds__(256, 2) void st_mma_kernel(
    const __nv_bfloat16* __restrict__ Hh, const __nv_bfloat16* __restrict__ Hl,
    const __nv_bfloat16* __restrict__ wsh, const __nv_bfloat16* __restrict__ wsl,
    const __nv_bfloat16* __restrict__ wth, const __nv_bfloat16* __restrict__ wtl,
    const float* __restrict__ bs, const float* __restrict__ bt,
    float* __restrict__ stout)
{
    extern __shared__ char sm[];
    uint32_t base = smem_to_u32(sm);
    uint32_t Ab0 = base,             Ab1 = base + STILE;
    uint32_t Bb0 = base + 2 * STILE, Bb1 = base + 3 * STILE;
    int tid = threadIdx.x, wid = tid >> 5, lane = tid & 31;
    int warp_m = wid & 1, warp_n = wid >> 1;
    int rowbase = blockIdx.x * 128;
    int ntile = blockIdx.y;
    const __nv_bfloat16* bwh = ntile ? wth : wsh;
    const __nv_bfloat16* bwl = ntile ? wtl : wsl;
    const float* bias = ntile ? bt : bs;

    st_load_chunk(Ab0, Bb0, Hh, bwh, rowbase, 0, tid);
    CP_COMMIT();

    uint32_t aoff = (uint32_t)((warp_m * 64 + (lane & 15)) * SSTR + ((lane >> 4) * 8) * 2);
    uint32_t boff = (uint32_t)((warp_n * 32 + ((lane >> 4) & 1) * 8 + (lane & 7)) * SSTR
                               + (((lane >> 3) & 1) * 8) * 2);

    float acc[4][4][4];
#pragma unroll
    for (int mi = 0; mi < 4; mi++)
#pragma unroll
        for (int ni = 0; ni < 4; ni++)
#pragma unroll
            for (int q = 0; q < 4; q++) acc[mi][ni][q] = 0.f;

    for (int idx = 0; idx < 24; idx++) {
        int cur = idx & 1;
        if (idx + 1 < 24) {
            int sg = (idx + 1) >> 3, k0 = ((idx + 1) & 7) * 64;
            const __nv_bfloat16* As = (sg == 1) ? Hl : Hh;
            const __nv_bfloat16* Bs = (sg == 2) ? bwl : bwh;
            st_load_chunk(cur ? Ab0 : Ab1, cur ? Bb0 : Bb1, As, Bs, rowbase, k0, tid);
            CP_COMMIT();
            CP_WAIT1();
        } else {
            CP_WAIT0();
        }
        __syncthreads();
        uint32_t Abc = cur ? Ab1 : Ab0;
        uint32_t Bbc = cur ? Bb1 : Bb0;
#pragma unroll
        for (int kc = 0; kc < 4; kc++) {
            uint32_t kb = kc * 32;
            uint32_t afrag[4][4], bfrag[4][2];
#pragma unroll
            for (int mi = 0; mi < 4; mi++)
                ldm_x4(afrag[mi], Abc + aoff + kb + (uint32_t)(mi * 16 * SSTR));
#pragma unroll
            for (int pr = 0; pr < 2; pr++) {
                uint32_t r4[4];
                ldm_x4(r4, Bbc + boff + kb + (uint32_t)(pr * 16 * SSTR));
                bfrag[pr * 2 + 0][0] = r4[0]; bfrag[pr * 2 + 0][1] = r4[1];
                bfrag[pr * 2 + 1][0] = r4[2]; bfrag[pr * 2 + 1][1] = r4[3];
            }
#pragma unroll
            for (int mi = 0; mi < 4; mi++)
#pragma unroll
                for (int ni = 0; ni < 4; ni++)
                    mma_bf16(acc[mi][ni], afrag[mi], bfrag[ni]);
        }
        __syncthreads();
    }

#pragma unroll
    for (int mi = 0; mi < 4; mi++) {
        int r0 = rowbase + warp_m * 64 + mi * 16 + (lane >> 2);
#pragma unroll
        for (int ni = 0; ni < 4; ni++) {
            int c0 = warp_n * 32 + ni * 8 + (lane & 3) * 2;
            float b0 = bias[c0], b1v = bias[c0 + 1];
#pragma unroll
            for (int h = 0; h < 2; h++) {
                int r = r0 + h * 8;
                float2 v;
                v.x = acc[mi][ni][h * 2 + 0] + b0;
                v.y = acc[mi][ni][h * 2 + 1] + b1v;
                *(float2*)(stout + (size_t)r * F_ + ntile * HALF_ + c0) = v;
            }
        }
    }
}

// ---------------- coupling epilogue ----------------
__global__ __launch_bounds__(256) void couple_kernel(
    const float* __restrict__ stin,
    const float* __restrict__ xa, int sxa,
    const float* __restrict__ xb, int sxb,
    float* __restrict__ yb,
    __nv_bfloat16* __restrict__ yh, __nv_bfloat16* __restrict__ yl,
    float* __restrict__ out, __nv_bfloat16* __restrict__ outb,
    int is_last, int accum)
{
    int warp = threadIdx.x >> 5, lane = threadIdx.x & 31;
    int r = blockIdx.x * 8 + warp;
    float4 s4 = ((const float4*)(stin + (size_t)r * F_))[lane];
    float4 t4 = ((const float4*)(stin + (size_t)r * F_ + HALF_))[lane];
    float4 xb4 = ((const float4*)(xb + (size_t)r * sxb))[lane];
    if (!is_last) {
        s4.x = tanhf(s4.x); s4.y = tanhf(s4.y);
        s4.z = tanhf(s4.z); s4.w = tanhf(s4.w);
    }
    float4 y;
    y.x = fmaf(xb4.x, expf(s4.x), t4.x);
    y.y = fmaf(xb4.y, expf(s4.y), t4.y);
    y.z = fmaf(xb4.z, expf(s4.z), t4.z);
    y.w = fmaf(xb4.w, expf(s4.w), t4.w);

    float js = s4.x + s4.y + s4.z + s4.w;
#pragma unroll
    for (int off = 16; off; off >>= 1) js += __shfl_down_sync(0xffffffff, js, off);
    if (lane == 0) g_jac[r] = accum ? g_jac[r] + js : js;

    if (!is_last) {
        ((float4*)(yb + (size_t)r * HALF_))[lane] = y;
        __nv_bfloat16 h0, h1, h2, h3, l0, l1, l2, l3;
        bsplit(y.x, h0, l0); bsplit(y.y, h1, l1);
        bsplit(y.z, h2, l2); bsplit(y.w, h3, l3);
        uint2 hv, lv;
        __nv_bfloat162 p01 = __halves2bfloat162(h0, h1), p23 = __halves2bfloat162(h2, h3);
        __nv_bfloat162 q01 = __halves2bfloat162(l0, l1), q23 = __halves2bfloat162(l2, l3);
        hv.x = *(uint32_t*)&p01; hv.y = *(uint32_t*)&p23;
        lv.x = *(uint32_t*)&q01; lv.y = *(uint32_t*)&q23;
        ((uint2*)(yh + (size_t)r * HALF_))[lane] = hv;
        ((uint2*)(yl + (size_t)r * HALF_))[lane] = lv;
    } else {
        float4 xa4 = ((const float4*)(xa + (size_t)r * sxa))[lane];
        ((float4*)(out + (size_t)r * F_))[lane] = y;
        ((float4*)(out + (size_t)r * F_ + HALF_))[lane] = xa4;
        uint2 u;
        u.x = pack_bf2(y.x, y.y); u.y = pack_bf2(y.z, y.w);
        ((uint2*)(outb + (size_t)r * F_))[lane] = u;
        u.x = pack_bf2(xa4.x, xa4.y); u.y = pack_bf2(xa4.z, xa4.w);
        ((uint2*)(outb + (size_t)r * F_ + HALF_))[lane] = u;
    }
}

// ---------------- bf16 mma distance GEMM + fused argmin (pair-decoupled) ----------------
__global__ __launch_bounds__(256, 1) void argmin_mma_kernel(
    const __nv_bfloat16* __restrict__ xb, const __nv_bfloat16* __restrict__ pb)
{
    extern __shared__ char dsmem[];
    __shared__ __align__(16) float s_nb[4][2][32];
    __shared__ float redv[TM][4];
    __shared__ int   redi[TM][4];

    uint32_t Abase = smem_to_u32(dsmem);
    uint32_t Bregion = Abase + TILE_BYTES;

    int tid = threadIdx.x;
    int wid = tid >> 5, lane = tid & 31;
    int warp_m = wid & 1;
    int warp_n = wid >> 1;
    int pt = warp_m * 32 + lane;
    int rowbase = blockIdx.x * TM;
    int split = blockIdx.y;
    int code0 = split * (K_ / NSPLIT);
    int barid = 1 + warp_n;

    uint32_t sliceBase[2] = { Bregion + (uint32_t)(warp_n * 2 + 0) * SLICE,
                              Bregion + (uint32_t)(warp_n * 2 + 1) * SLICE };

#pragma unroll
    for (int i = 0; i < 16; i++) {
        int e = tid + i * 256;
        int r = e >> 5, c = e & 31;
        cp16(Abase + r * STRB + c * 16,
             (const char*)(xb + (size_t)(rowbase + r) * TK) + c * 16);
    }
#pragma unroll
    for (int i = 0; i < 16; i++) {
        int j = pt + i * 64;
        int r = j >> 5, c = j & 31;
        cp16(sliceBase[0] + r * STRB + c * 16,
             (const char*)(pb + (size_t)(code0 + warp_n * 32 + r) * TK) + c * 16);
    }
    if (pt < 32) s_nb[warp_n][0][pt] = g_nb[code0 + warp_n * 32 + pt];
    CP_COMMIT();
    CP_WAIT0();
    __syncthreads();

    uint32_t aoff = (uint32_t)((warp_m * 64 + (lane & 15)) * STRB + ((lane >> 4) * 8) * 2);
    uint32_t boff = (uint32_t)((((lane >> 4) & 1) * 8 + (lane & 7)) * STRB
                               + (((lane >> 3) & 1) * 8) * 2);

    float minv[8];
    int   mini[8];
#pragma unroll
    for (int i = 0; i < 8; i++) { minv[i] = 3.4e38f; mini[i] = 0; }

    for (int t = 0; t < NT; t++) {
        int cb = t & 1;
        if (t + 1 < NT) {
            int nb_ = (t + 1) & 1;
            int codeN = code0 + (t + 1) * TN;
#pragma unroll
            for (int i = 0; i < 16; i++) {
                int j = pt + i * 64;
                int r = j >> 5, c = j & 31;
                cp16(sliceBase[nb_] + r * STRB + c * 16,
                     (const char*)(pb + (size_t)(codeN + warp_n * 32 + r) * TK) + c * 16);
            }
            if (pt < 32) s_nb[warp_n][nb_][pt] = g_nb[codeN + warp_n * 32 + pt];
            CP_COMMIT();
            CP_WAIT1();
        } else {
            CP_WAIT0();
        }
        PAIR_BAR(barid);

        float acc[4][4][4];
#pragma unroll
        for (int mi = 0; mi < 4; mi++)
#pragma unroll
            for (int ni = 0; ni < 4; ni++)
#pragma unroll
                for (int q = 0; q < 4; q++) acc[mi][ni][q] = 0.f;

#pragma unroll
        for (int kc = 0; kc < 16; kc++) {
            uint32_t kb = kc * 32;
            uint32_t afrag[4][4], bfrag[4][2];
#pragma unroll
            for (int mi = 0; mi < 4; mi++)
                ldm_x4(afrag[mi], Abase + aoff + kb + (uint32_t)(mi * 16 * STRB));
#pragma unroll
            for (int pr = 0; pr < 2; pr++) {
                uint32_t r4[4];
                ldm_x4(r4, sliceBase[cb] + boff + kb + (uint32_t)(pr * 16 * STRB));
                bfrag[pr * 2 + 0][0] = r4[0]; bfrag[pr * 2 + 0][1] = r4[1];
                bfrag[pr * 2 + 1][0] = r4[2]; bfrag[pr * 2 + 1][1] = r4[3];
            }
#pragma unroll
            for (int mi = 0; mi < 4; mi++)
#pragma unroll
                for (int ni = 0; ni < 4; ni++)
                    mma_bf16(acc[mi][ni], afrag[mi], bfrag[ni]);
        }

        int ctile = code0 + t * TN;
#pragma unroll
        for (int mi = 0; mi < 4; mi++)
#pragma unroll
            for (int ni = 0; ni < 4; ni++)
#pragma unroll
                for (int q = 0; q < 4; q++) {
                    int nloc = ni * 8 + (lane & 3) * 2 + (q & 1);
                    float v = fmaf(-2.f, acc[mi][ni][q], s_nb[warp_n][cb][nloc]);
                    int ridx = mi * 2 + (q >> 1);
                    if (v < minv[ridx]) { minv[ridx] = v; mini[ridx] = ctile + warp_n * 32 + nloc; }
                }

        PAIR_BAR(barid);
    }

#pragma unroll
    for (int ridx = 0; ridx < 8; ridx++) {
        float v = minv[ridx]; int ii = mini[ridx];
#pragma unroll
        for (int off = 1; off <= 2; off <<= 1) {
            float ov = __shfl_xor_sync(0xffffffff, v, off);
            int   oi = __shfl_xor_sync(0xffffffff, ii, off);
            if (ov < v || (ov == v && oi < ii)) { v = ov; ii = oi; }
        }
        if ((lane & 3) == 0) {
            int row = warp_m * 64 + (ridx >> 1) * 16 + (ridx & 1) * 8 + (lane >> 2);
            redv[row][warp_n] = v;
            redi[row][warp_n] = ii;
        }
    }
    __syncthreads();
    if (tid < TM) {
        float bv = redv[tid][0]; int bi = redi[tid][0];
#pragma unroll
        for (int q = 1; q < 4; q++) {
            float v = redv[tid][q]; int ii = redi[tid][q];
            if (v < bv || (v == bv && ii < bi)) { bv = v; bi = ii; }
        }
        g_pmin[(size_t)(rowbase + tid) * NSPLIT + split] = bv;
        g_pidx[(size_t)(rowbase + tid) * NSPLIT + split] = bi;
    }
}

// ---------------- loss ----------------
__global__ __launch_bounds__(256) void loss_kernel(
    const float* __restrict__ x, const float* __restrict__ prior)
{
    int warp = threadIdx.x >> 5, lane = threadIdx.x & 31;
    int r = blockIdx.x * 8 + warp;
    float v = 3.4e38f; int idx = 0x7fffffff;
    if (lane < NSPLIT) { v = g_pmin[(size_t)r * NSPLIT + lane]; idx = g_pidx[(size_t)r * NSPLIT + lane]; }
#pragma unroll
    for (int off = 8; off; off >>= 1) {
        float ov = __shfl_down_sync(0xffffffff, v, off);
        int   oi = __shfl_down_sync(0xffffffff, idx, off);
        if (ov < v || (ov == v && oi < idx)) { v = ov; idx = oi; }
    }
    idx = __shfl_sync(0xffffffff, idx, 0);
    float ss = 0.f;
#pragma unroll
    for (int f = lane; f < F_; f += 32) {
        float d = x[(size_t)r * F_ + f] - prior[(size_t)idx * F_ + f];
        ss = fmaf(d, d, ss);
    }
#pragma unroll
    for (int off = 16; off; off >>= 1) ss += __shfl_down_sync(0xffffffff, ss, off);
    __shared__ float part[8];
    if (lane == 0) part[warp] = fmaf(0.625f, ss, -g_jac[r]);
    __syncthreads();
    if (threadIdx.x == 0) {
        float s = 0.f;
#pragma unroll
        for (int i = 0; i < 8; i++) s += part[i];
        g_partial[blockIdx.x] = s;
    }
}

__global__ __launch_bounds__(256) void final_kernel(float* out, int out_size) {
    __shared__ float sm[256];
    int tid = threadIdx.x;
    float s = 0.f;
    for (int i = tid; i < B_ / 8; i += 256) s += g_partial[i];
    sm[tid] = s;
    __syncthreads();
    for (int st = 128; st; st >>= 1) { if (tid < st) sm[tid] += sm[tid + st]; __syncthreads(); }
    float loss = sm[0] / (float)B_;
    for (int i = B_ * F_ + tid; i < out_size; i += 256) out[i] = loss;
}

// ---------------- launch ----------------
static void* sym(const void* s) { void* p; cudaGetSymbolAddress(&p, s); return p; }

extern "C" void kernel_launch(void* const* d_in, const int* in_sizes, int n_in,
                              void* d_out, int out_size) {
    const float* x0    = (const float*)d_in[0];
    const float* W1    = (const float*)d_in[1];
    const float* b1    = (const float*)d_in[2];
    const float* Ws    = (const float*)d_in[3];
    const float* bs    = (const float*)d_in[4];
    const float* Wt    = (const float*)d_in[5];
    const float* bt    = (const float*)d_in[6];
    const float* prior = (const float*)d_in[7];
    float* out = (float*)d_out;

    __nv_bfloat16* gpb  = (__nv_bfloat16*)sym(g_pb);
    __nv_bfloat16* gxb  = (__nv_bfloat16*)sym(g_xb);
    __nv_bfloat16* ahB[2] = { (__nv_bfloat16*)sym(g_ah0), (__nv_bfloat16*)sym(g_ah1) };
    __nv_bfloat16* alB[2] = { (__nv_bfloat16*)sym(g_al0), (__nv_bfloat16*)sym(g_al1) };
    __nv_bfloat16* gHh  = (__nv_bfloat16*)sym(g_Hh);
    __nv_bfloat16* gHl  = (__nv_bfloat16*)sym(g_Hl);
    float* gst = (float*)sym(g_st);
    float* yB[2] = { (float*)sym(g_y0), (float*)sym(g_y1) };
    __nv_bfloat16* w1h = (__nv_bfloat16*)sym(g_w1h);
    __nv_bfloat16* w1l = (__nv_bfloat16*)sym(g_w1l);
    __nv_bfloat16* wsh = (__nv_bfloat16*)sym(g_wsh);
    __nv_bfloat16* wsl = (__nv_bfloat16*)sym(g_wsl);
    __nv_bfloat16* wth = (__nv_bfloat16*)sym(g_wth);
    __nv_bfloat16* wtl = (__nv_bfloat16*)sym(g_wtl);

    static int smem_set = 0;
    const int ASMEM = TILE_BYTES + 8 * SLICE;   // 202752
    const int HSMEM = 4 * HTILE;                // 139264
    const int SSMEM = 4 * STILE;                // 73728
    if (!smem_set) {
        cudaFuncSetAttribute(argmin_mma_kernel, cudaFuncAttributeMaxDynamicSharedMemorySize, ASMEM);
        cudaFuncSetAttribute(hidden_mma_kernel, cudaFuncAttributeMaxDynamicSharedMemorySize, HSMEM);
        cudaFuncSetAttribute(st_mma_kernel, cudaFuncAttributeMaxDynamicSharedMemorySize, SSMEM);
        smem_set = 1;
    }

    // prep (consolidated)
    nbcvt_kernel<<<K_ / 8, 256>>>(prior, gpb);
    wsplit3_kernel<<<dim3((L_ * HALF_ * H_) / 256, 3), 256>>>(
        W1, Ws, Wt, w1h, w1l, wsh, wsl, wth, wtl);
    xsplit_kernel<<<(B_ * HALF_) / 256, 256>>>(x0, ahB[0], alB[0]);

    // flow
    const float* XA = x0;        int sxa = F_;
    const float* XB = x0 + HALF_; int sxb = F_;
    for (int l = 0; l < L_; l++) {
        hidden_mma_kernel<<<dim3(B_ / 128, H_ / 128), 256, HSMEM>>>(
            ahB[l & 1], alB[l & 1],
            w1h + (size_t)l * H_ * HALF_, w1l + (size_t)l * H_ * HALF_,
            b1 + (size_t)l * H_, gHh, gHl);
        st_mma_kernel<<<dim3(B_ / 128, 2), 256, SSMEM>>>(
            gHh, gHl,
            wsh + (size_t)l * HALF_ * H_, wsl + (size_t)l * HALF_ * H_,
            wth + (size_t)l * HALF_ * H_, wtl + (size_t)l * HALF_ * H_,
            bs + (size_t)l * HALF_, bt + (size_t)l * HALF_, gst);
        int last = (l == L_ - 1);
        couple_kernel<<<B_ / 8, 256>>>(
            gst, XA, sxa, XB, sxb,
            yB[l & 1], ahB[(l + 1) & 1], alB[(l + 1) & 1],
            out, gxb, last, l > 0);
        XB = XA; sxb = sxa;
        XA = yB[l & 1]; sxa = HALF_;
    }

    // VQ argmin + loss
    argmin_mma_kernel<<<dim3(B_ / TM, NSPLIT), 256, ASMEM>>>(gxb, gpb);
    loss_kernel<<<B_ / 8, 256>>>(out, prior);
    if (out_size > B_ * F_)
        final_kernel<<<1, 256>>>(out, out_size);
}